// round 7
// baseline (speedup 1.0000x reference)
#include <cuda_runtime.h>

#define BATCH 8
#define NTOK  1024
#define DDIM  64
#define NF    11
#define SROW  12                       // padded feature row stride (words)

#define K1_WARPS   8
#define K1_RPW     2
#define K1_ROWS    (K1_WARPS * K1_RPW) // 16 rows per block
#define K1_THREADS 256
#define K1_BPB     (NTOK / K1_ROWS)    // 64 blocks per batch -> grid 512

__device__ float g_inv_s[BATCH * NTOK];   // per-row 1/S scratch

__global__ __launch_bounds__(K1_THREADS, 3)
void featsim_exp_kernel(const float* __restrict__ x,
                        const int*   __restrict__ xlen,
                        const float* __restrict__ fi,
                        float*       __restrict__ out)
{
    __shared__ float sfeat[NTOK * SROW];   // 48 KB

    const int tid  = threadIdx.x;
    const int wid  = tid >> 5;
    const int lane = tid & 31;

    const int b  = blockIdx.x / K1_BPB;
    const int i0 = (blockIdx.x % K1_BPB) * K1_ROWS;

    const int len     = xlen[b];
    const int nchunks = (len + 31) >> 5;
    const int nstage  = nchunks << 5;

    const float* xb = x + (size_t)b * NTOK * DDIM;

    // Stage j-features (first nstage tokens): 3 float4 per token, stride 12.
    {
        const float4* xb4 = (const float4*)xb;
        for (int idx = tid; idx < nstage * 3; idx += K1_THREADS) {
            int j = idx / 3;
            int q = idx - j * 3;
            *(float4*)&sfeat[j * SROW + q * 4] = xb4[j * 16 + q];
        }
    }

    float w[NF];
#pragma unroll
    for (int f = 0; f < NF; f++) w[f] = fi[f];

    // i-row features from global (broadcast LDG.128, L2-hot). All rows computed
    // (reference masks columns only).
    const int ibase = i0 + wid * K1_RPW;
    float ifeat[K1_RPW][NF];
#pragma unroll
    for (int r = 0; r < K1_RPW; r++) {
        const float4* rp = (const float4*)(xb + (size_t)(ibase + r) * DDIM);
        float4 t0 = rp[0], t1 = rp[1], t2 = rp[2];
        ifeat[r][0]=t0.x; ifeat[r][1]=t0.y; ifeat[r][2]=t0.z; ifeat[r][3]=t0.w;
        ifeat[r][4]=t1.x; ifeat[r][5]=t1.y; ifeat[r][6]=t1.z; ifeat[r][7]=t1.w;
        ifeat[r][8]=t2.x; ifeat[r][9]=t2.y; ifeat[r][10]=t2.z;
    }

    __syncthreads();

    float S[K1_RPW];
#pragma unroll
    for (int r = 0; r < K1_RPW; r++) S[r] = 0.0f;

    float* orow0 = out + ((size_t)b * NTOK + ibase) * NTOK;

    // Dynamic chunk loop: no per-chunk divergence, unroll-4 batches the LDS.
#pragma unroll 4
    for (int c = 0; c < nchunks; c++) {
        const int j = (c << 5) + lane;
        float4 j0 = *(const float4*)&sfeat[j * SROW];
        float4 j1 = *(const float4*)&sfeat[j * SROW + 4];
        float4 j2 = *(const float4*)&sfeat[j * SROW + 8];
        const bool jv = (j < len);
#pragma unroll
        for (int r = 0; r < K1_RPW; r++) {
            float a0 = w[0]*fabsf(ifeat[r][0]-j0.x) + w[1]*fabsf(ifeat[r][1]-j0.y);
            float a1 = w[2]*fabsf(ifeat[r][2]-j0.z) + w[3]*fabsf(ifeat[r][3]-j0.w);
            float a2 = w[4]*fabsf(ifeat[r][4]-j1.x) + w[5]*fabsf(ifeat[r][5]-j1.y);
            float a3 = w[6]*fabsf(ifeat[r][6]-j1.z) + w[7]*fabsf(ifeat[r][7]-j1.w);
            float a4 = w[8]*fabsf(ifeat[r][8]-j2.x) + w[9]*fabsf(ifeat[r][9]-j2.y);
            float a5 = w[10]*fabsf(ifeat[r][10]-j2.z);
            float v  = ((a0 + a1) + (a2 + a3)) + (a4 + a5);
            float m  = (v < 1.0f) ? -v : 0.0f;     // softmax shift M=0 (exact)
            float e  = jv ? __expf(m) : 0.0f;
            S[r] += e;
            orow0[r * NTOK + j] = e;               // unnormalized; final after scale
        }
    }

    // Tail columns (j >= nstage) are exactly zero in the final output.
    {
        const float4 z = make_float4(0.f, 0.f, 0.f, 0.f);
#pragma unroll
        for (int r = 0; r < K1_RPW; r++) {
            float4* o4 = (float4*)(orow0 + r * NTOK);
            for (int q = (nstage >> 2) + lane; q < (NTOK >> 2); q += 32)
                o4[q] = z;
        }
    }

    // Row sums -> 1/S scratch.
#pragma unroll
    for (int r = 0; r < K1_RPW; r++) {
#pragma unroll
        for (int s = 16; s > 0; s >>= 1)
            S[r] += __shfl_xor_sync(0xffffffffu, S[r], s);
        if (lane == 0)
            g_inv_s[b * NTOK + ibase + r] = __fdividef(1.0f, S[r]);  // len>=1 -> S>0
    }
}

// One block per row: scale the valid-column prefix in place (zeros untouched).
__global__ __launch_bounds__(256, 8)
void featsim_scale_kernel(const int* __restrict__ xlen,
                          float*     __restrict__ out)
{
    const int row = blockIdx.x;               // 0..8191
    const int b   = row >> 10;
    const int len = xlen[b];
    const int nstage = ((len + 31) >> 5) << 5;
    const int col = threadIdx.x << 2;
    if (col < nstage) {
        const float inv = g_inv_s[row];       // broadcast load
        float4* p = (float4*)(out + (size_t)row * NTOK) + threadIdx.x;
        float4 v = *p;
        v.x *= inv; v.y *= inv; v.z *= inv; v.w *= inv;
        *p = v;
    }
}

extern "C" void kernel_launch(void* const* d_in, const int* in_sizes, int n_in,
                              void* d_out, int out_size)
{
    const float* x    = (const float*)d_in[0];
    const int*   xlen = (const int*)  d_in[1];
    const float* fi   = (const float*)d_in[2];
    float*       out  = (float*)d_out;

    featsim_exp_kernel<<<BATCH * K1_BPB, K1_THREADS>>>(x, xlen, fi, out);  // 512 blocks
    featsim_scale_kernel<<<BATCH * NTOK, 256>>>(xlen, out);                // 8192 blocks
}

// round 10
// speedup vs baseline: 1.1758x; 1.1758x over previous
#include <cuda_runtime.h>

#define BATCH 8
#define NTOK  1024
#define DDIM  64
#define NF    11
#define SROW  12                       // padded feature row stride (words)

#define K1_WARPS   8
#define K1_RPW     2
#define K1_ROWS    (K1_WARPS * K1_RPW) // 16 rows per block
#define K1_THREADS 256
#define K1_BPB     (NTOK / K1_ROWS)    // 64 blocks per batch -> grid 512

__global__ __launch_bounds__(K1_THREADS, 3)
void featsim_kernel(const float* __restrict__ x,
                    const int*   __restrict__ xlen,
                    const float* __restrict__ fi,
                    float*       __restrict__ out)
{
    __shared__ float sfeat[NTOK * SROW];   // 48 KB

    const int tid  = threadIdx.x;
    const int wid  = tid >> 5;
    const int lane = tid & 31;

    const int b  = blockIdx.x / K1_BPB;
    const int i0 = (blockIdx.x % K1_BPB) * K1_ROWS;

    const int len     = xlen[b];
    const int nchunks = (len + 31) >> 5;
    const int nstage  = nchunks << 5;

    const float* xb = x + (size_t)b * NTOK * DDIM;

    // Stage j-features (first nstage tokens): 3 float4 per token, stride 12.
    {
        const float4* xb4 = (const float4*)xb;
        for (int idx = tid; idx < nstage * 3; idx += K1_THREADS) {
            int j = idx / 3;
            int q = idx - j * 3;
            *(float4*)&sfeat[j * SROW + q * 4] = xb4[j * 16 + q];
        }
    }

    float w[NF];
#pragma unroll
    for (int f = 0; f < NF; f++) w[f] = fi[f];

    // i-row features from global (broadcast LDG.128, L2-hot). All rows computed
    // (reference masks columns only).
    const int ibase = i0 + wid * K1_RPW;
    float ifeat[K1_RPW][NF];
#pragma unroll
    for (int r = 0; r < K1_RPW; r++) {
        const float4* rp = (const float4*)(xb + (size_t)(ibase + r) * DDIM);
        float4 t0 = rp[0], t1 = rp[1], t2 = rp[2];
        ifeat[r][0]=t0.x; ifeat[r][1]=t0.y; ifeat[r][2]=t0.z; ifeat[r][3]=t0.w;
        ifeat[r][4]=t1.x; ifeat[r][5]=t1.y; ifeat[r][6]=t1.z; ifeat[r][7]=t1.w;
        ifeat[r][8]=t2.x; ifeat[r][9]=t2.y; ifeat[r][10]=t2.z;
    }

    __syncthreads();

    float S[K1_RPW];
#pragma unroll
    for (int r = 0; r < K1_RPW; r++) S[r] = 0.0f;

    float* orow0 = out + ((size_t)b * NTOK + ibase) * NTOK;

    // Dynamic chunk loop: no per-chunk divergence, unroll-4 batches the LDS.
#pragma unroll 4
    for (int c = 0; c < nchunks; c++) {
        const int j = (c << 5) + lane;
        float4 j0 = *(const float4*)&sfeat[j * SROW];
        float4 j1 = *(const float4*)&sfeat[j * SROW + 4];
        float4 j2 = *(const float4*)&sfeat[j * SROW + 8];
        const bool jv = (j < len);
#pragma unroll
        for (int r = 0; r < K1_RPW; r++) {
            float a0 = w[0]*fabsf(ifeat[r][0]-j0.x) + w[1]*fabsf(ifeat[r][1]-j0.y);
            float a1 = w[2]*fabsf(ifeat[r][2]-j0.z) + w[3]*fabsf(ifeat[r][3]-j0.w);
            float a2 = w[4]*fabsf(ifeat[r][4]-j1.x) + w[5]*fabsf(ifeat[r][5]-j1.y);
            float a3 = w[6]*fabsf(ifeat[r][6]-j1.z) + w[7]*fabsf(ifeat[r][7]-j1.w);
            float a4 = w[8]*fabsf(ifeat[r][8]-j2.x) + w[9]*fabsf(ifeat[r][9]-j2.y);
            float a5 = w[10]*fabsf(ifeat[r][10]-j2.z);
            float v  = ((a0 + a1) + (a2 + a3)) + (a4 + a5);
            float m  = (v < 1.0f) ? -v : 0.0f;     // softmax shift M=0 (exact)
            float e  = jv ? __expf(m) : 0.0f;
            S[r] += e;
            orow0[r * NTOK + j] = e;               // unnormalized for now
        }
    }

    // Tail columns (j >= nstage) are exactly zero in the final output.
    {
        const float4 z = make_float4(0.f, 0.f, 0.f, 0.f);
#pragma unroll
        for (int r = 0; r < K1_RPW; r++) {
            float4* o4 = (float4*)(orow0 + r * NTOK);
            for (int q = (nstage >> 2) + lane; q < (NTOK >> 2); q += 32)
                o4[q] = z;
        }
    }

    // Row sums.
#pragma unroll
    for (int r = 0; r < K1_RPW; r++) {
#pragma unroll
        for (int s = 16; s > 0; s >>= 1)
            S[r] += __shfl_xor_sync(0xffffffffu, S[r], s);
    }

    // In-kernel renormalize: re-read our just-written rows (L1/L2-hot) and
    // scale in place. __syncwarp orders the warp's stores before the re-read
    // (whole row is produced by this warp; no cross-warp hazard).
    __syncwarp();
#pragma unroll
    for (int r = 0; r < K1_RPW; r++) {
        const float inv = __fdividef(1.0f, S[r]);   // len >= 1 -> S > 0
        float4* o4 = (float4*)(orow0 + r * NTOK);
        const int nq = nstage >> 2;                 // float4s in valid prefix
        for (int q = lane; q < nq; q += 32) {       // <= 8 iters
            float4 v = o4[q];
            v.x *= inv; v.y *= inv; v.z *= inv; v.w *= inv;
            o4[q] = v;
        }
    }
}

extern "C" void kernel_launch(void* const* d_in, const int* in_sizes, int n_in,
                              void* d_out, int out_size)
{
    const float* x    = (const float*)d_in[0];
    const int*   xlen = (const int*)  d_in[1];
    const float* fi   = (const float*)d_in[2];
    float*       out  = (float*)d_out;

    featsim_kernel<<<BATCH * K1_BPB, K1_THREADS>>>(x, xlen, fi, out);  // 512 blocks
}